// round 9
// baseline (speedup 1.0000x reference)
#include <cuda_runtime.h>
#include <cstdint>

// ---------------------------------------------------------------------------
// Shapes
// ---------------------------------------------------------------------------
#define BT   12
#define CF   1024
#define CQ   128
#define NTOK 2401
#define NP   2432
#define HF   49

// ---------------------------------------------------------------------------
// Scratch
// ---------------------------------------------------------------------------
__device__ float g_X  [(size_t)BT * CF * NP];   // [bt][c][n]
__device__ float g_XT [(size_t)BT * NP * CF];   // [bt][n][c]
__device__ float g_QT [(size_t)BT * NP * CQ];   // [bt][n][o]
__device__ float g_KT [(size_t)BT * NP * CQ];   // [bt][m][o]
__device__ float g_V  [(size_t)BT * CF * NP];   // [bt][c][n]
__device__ float g_ATT[(size_t)BT * NP * NP];   // [bt][n][m]

__device__ __forceinline__ uint32_t f2tf(float f) {
    uint32_t u; asm("cvt.rna.tf32.f32 %0, %1;" : "=r"(u) : "f"(f)); return u;
}
__device__ __forceinline__ uint32_t u2tf(uint32_t x) {
    uint32_t u; asm("cvt.rna.tf32.f32 %0, %1;" : "=r"(u) : "f"(__uint_as_float(x))); return u;
}
__device__ __forceinline__ uint32_t smem_u32(const void* p) {
    uint32_t a;
    asm("{ .reg .u64 t; cvta.to.shared.u64 t, %1; cvt.u32.u64 %0, t; }" : "=r"(a) : "l"(p));
    return a;
}

__device__ __forceinline__ void mma_tf32(float c[4], const uint32_t a[4], const uint32_t b[2]) {
    asm volatile(
        "mma.sync.aligned.m16n8k8.row.col.f32.tf32.tf32.f32 "
        "{%0,%1,%2,%3}, {%4,%5,%6,%7}, {%8,%9}, {%0,%1,%2,%3};"
        : "+f"(c[0]), "+f"(c[1]), "+f"(c[2]), "+f"(c[3])
        : "r"(a[0]), "r"(a[1]), "r"(a[2]), "r"(a[3]), "r"(b[0]), "r"(b[1]));
}

#define CP_ASYNC16(dst_u32, src_ptr) \
    asm volatile("cp.async.cg.shared.global [%0], [%1], 16;" :: "r"(dst_u32), "l"(src_ptr) : "memory")
#define CP_COMMIT() asm volatile("cp.async.commit_group;" ::: "memory")
#define CP_WAIT0()  asm volatile("cp.async.wait_group 0;" ::: "memory")
#define CP_WAIT1()  asm volatile("cp.async.wait_group 1;" ::: "memory")

// ---------------------------------------------------------------------------
// 1a) X[bt][c][n]  (zero-padded n)
// ---------------------------------------------------------------------------
__global__ void build_x_kernel(const float* __restrict__ img,
                               const float* __restrict__ tac) {
    int n = blockIdx.x * 256 + threadIdx.x;
    int c = blockIdx.y, bt = blockIdx.z;
    if (n >= NP) return;
    float v = 0.0f;
    if (n < NTOK) {
        int i = n / HF, j = n % HF;
        v = (c < 512)
            ? tac[(((size_t)bt * 512 + c) * 7 + (i / 7)) * 7 + (j / 7)]
            : img[(((size_t)bt * 512 + (c - 512)) * 7 + (i % 7)) * 7 + (j % 7)];
    }
    g_X[((size_t)bt * CF + c) * NP + n] = v;
}

// ---------------------------------------------------------------------------
// 1b) XT[bt][n][c]  (zero rows for n >= NTOK)
// ---------------------------------------------------------------------------
__global__ void build_xt_kernel(const float* __restrict__ img,
                                const float* __restrict__ tac) {
    int c = blockIdx.x * 256 + threadIdx.x;
    int n = blockIdx.y, bt = blockIdx.z;
    if (c >= CF) return;
    float v = 0.0f;
    if (n < NTOK) {
        int i = n / HF, j = n % HF;
        v = (c < 512)
            ? tac[(((size_t)bt * 512 + c) * 7 + (i / 7)) * 7 + (j / 7)]
            : img[(((size_t)bt * 512 + (c - 512)) * 7 + (i % 7)) * 7 + (j % 7)];
    }
    g_XT[((size_t)bt * NP + n) * CF + c] = v;
}

// ---------------------------------------------------------------------------
// 2) row softmax (m < 2401), zero padding columns
// ---------------------------------------------------------------------------
__global__ __launch_bounds__(256)
void softmax_kernel() {
    __shared__ float row[NTOK];
    __shared__ float red[256];
    const int n = blockIdx.x, bt = blockIdx.y;
    float* base = g_ATT + ((size_t)bt * NP + n) * NP;
    const int t = threadIdx.x;

    float mx = -1e30f;
    for (int m = t; m < NTOK; m += 256) { float v = base[m]; row[m] = v; mx = fmaxf(mx, v); }
    red[t] = mx; __syncthreads();
    for (int s = 128; s > 0; s >>= 1) { if (t < s) red[t] = fmaxf(red[t], red[t + s]); __syncthreads(); }
    mx = red[0]; __syncthreads();

    float sum = 0.0f;
    for (int m = t; m < NTOK; m += 256) { float e = __expf(row[m] - mx); row[m] = e; sum += e; }
    red[t] = sum; __syncthreads();
    for (int s = 128; s > 0; s >>= 1) { if (t < s) red[t] += red[t + s]; __syncthreads(); }
    float inv = 1.0f / red[0];

    for (int m = t; m < NTOK; m += 256) base[m] = row[m] * inv;
    for (int m = NTOK + t; m < NP; m += 256) base[m] = 0.0f;
}

// ---------------------------------------------------------------------------
// Shared tiling constants (stride-36 layout, conflict-free scalar LDS)
// ---------------------------------------------------------------------------
#define LDS_S 36
#define TILEW (128 * LDS_S)            // words per 128x32 tile
#define SMEM_T (4 * TILEW * 4)         // 73728 B: raw A0,B0,A1,B1 double buffer

// ---------------------------------------------------------------------------
// 3) SPLIT=1 tf32 GEMM, cp.async double-buffered, 128 threads (4 warps 2x2),
//    warp tile 64x64 (LDS/MMA = 1.0), 2 CTAs/SM.
//    C[M,N] = A[M,K] @ B[N,K]^T (both K-major).
//    EPI 0: C = acc + bias[row]
//    EPI 1: C = gamma*acc + X[row][col], col<NTOK
// ---------------------------------------------------------------------------
template <int EPI>
__global__ __launch_bounds__(128, 2)
void gemm_async_kernel(const float* __restrict__ A, int lda, size_t strideA,
                       const float* __restrict__ B, int ldb, size_t strideB,
                       int K,
                       const float* __restrict__ bias,
                       const float* __restrict__ gamma,
                       const float* __restrict__ Xres,
                       float* __restrict__ C, int ldc, size_t strideC) {
    extern __shared__ uint32_t sm[];
    const uint32_t smem_base = smem_u32(sm);

    const int bt = blockIdx.z;
    const int m0 = blockIdx.x * 128;
    const int n0 = blockIdx.y * 128;
    const float* Ab = A + (size_t)bt * strideA + (size_t)m0 * lda;
    const float* Bb = B + (size_t)bt * strideB + (size_t)n0 * ldb;

    const int t = threadIdx.x;
    const int wid = t >> 5, lane = t & 31;
    const int warp_m = wid & 1, warp_n = wid >> 1;   // 2 x 2
    const int l4 = lane >> 2, lm = lane & 3;

    // producer mapping: 1 thread per row, 8 x 16B per tile
    const float* aRow = Ab + (size_t)t * lda;
    const float* bRow = Bb + (size_t)t * ldb;
    const uint32_t sA0 = smem_base + t * LDS_S * 4;
    const uint32_t sB0 = sA0 + TILEW * 4;

    float acc[4][8][4];
    #pragma unroll
    for (int mi = 0; mi < 4; mi++)
        #pragma unroll
        for (int ni = 0; ni < 8; ni++)
            #pragma unroll
            for (int r = 0; r < 4; r++) acc[mi][ni][r] = 0.0f;

    const int NCH = K / 32;

    #pragma unroll
    for (int q = 0; q < 8; q++) {
        CP_ASYNC16(sA0 + q * 16, aRow + q * 4);
        CP_ASYNC16(sB0 + q * 16, bRow + q * 4);
    }
    CP_COMMIT();

    for (int ch = 0; ch < NCH; ch++) {
        const int buf = ch & 1;
        if (ch + 1 < NCH) {
            const int k1 = (ch + 1) * 32;
            const uint32_t dA = sA0 + (buf ^ 1) * (2 * TILEW * 4);
            const uint32_t dB = sB0 + (buf ^ 1) * (2 * TILEW * 4);
            #pragma unroll
            for (int q = 0; q < 8; q++) {
                CP_ASYNC16(dA + q * 16, aRow + k1 + q * 4);
                CP_ASYNC16(dB + q * 16, bRow + k1 + q * 4);
            }
            CP_COMMIT();
            CP_WAIT1();
        } else {
            CP_WAIT0();
        }
        __syncthreads();

        const uint32_t* as = sm + buf * 2 * TILEW;
        const uint32_t* bs = as + TILEW;
        #pragma unroll
        for (int g = 0; g < 4; g++) {
            const int kk = g * 8;
            uint32_t b[8][2];
            #pragma unroll
            for (int ni = 0; ni < 8; ni++) {
                const int base = (warp_n * 64 + ni * 8 + l4) * LDS_S + kk + lm;
                b[ni][0] = u2tf(bs[base]);
                b[ni][1] = u2tf(bs[base + 4]);
            }
            #pragma unroll
            for (int mi = 0; mi < 4; mi++) {
                const int base = (warp_m * 64 + mi * 16 + l4) * LDS_S + kk + lm;
                uint32_t a[4];
                a[0] = u2tf(as[base]);
                a[1] = u2tf(as[base + 8 * LDS_S]);
                a[2] = u2tf(as[base + 4]);
                a[3] = u2tf(as[base + 8 * LDS_S + 4]);
                #pragma unroll
                for (int ni = 0; ni < 8; ni++) mma_tf32(acc[mi][ni], a, b[ni]);
            }
        }
        __syncthreads();
    }

    float* Cb = C + (size_t)bt * strideC;
    if (EPI == 0) {
        #pragma unroll
        for (int mi = 0; mi < 4; mi++) {
            const int gr = m0 + warp_m * 64 + mi * 16 + l4;
            const float bv0 = bias[gr], bv8 = bias[gr + 8];
            #pragma unroll
            for (int ni = 0; ni < 8; ni++) {
                const int gc = n0 + warp_n * 64 + ni * 8 + lm * 2;
                float2 o0 = { acc[mi][ni][0] + bv0, acc[mi][ni][1] + bv0 };
                float2 o1 = { acc[mi][ni][2] + bv8, acc[mi][ni][3] + bv8 };
                *reinterpret_cast<float2*>(&Cb[(size_t)gr * ldc + gc]) = o0;
                *reinterpret_cast<float2*>(&Cb[(size_t)(gr + 8) * ldc + gc]) = o1;
            }
        }
    } else {
        const float g = __ldg(gamma);
        const float* Xb = Xres + (size_t)bt * CF * NP;
        #pragma unroll
        for (int mi = 0; mi < 4; mi++) {
            const int gr = m0 + warp_m * 64 + mi * 16 + l4;
            #pragma unroll
            for (int ni = 0; ni < 8; ni++) {
                const int gc = n0 + warp_n * 64 + ni * 8 + lm * 2;
                if (gc < NTOK)
                    Cb[(size_t)gr * ldc + gc] = g * acc[mi][ni][0] + Xb[(size_t)gr * NP + gc];
                if (gc + 1 < NTOK)
                    Cb[(size_t)gr * ldc + gc + 1] = g * acc[mi][ni][1] + Xb[(size_t)gr * NP + gc + 1];
                if (gc < NTOK)
                    Cb[(size_t)(gr + 8) * ldc + gc] = g * acc[mi][ni][2] + Xb[(size_t)(gr + 8) * NP + gc];
                if (gc + 1 < NTOK)
                    Cb[(size_t)(gr + 8) * ldc + gc + 1] = g * acc[mi][ni][3] + Xb[(size_t)(gr + 8) * NP + gc + 1];
            }
        }
    }
}

// ---------------------------------------------------------------------------
// 4) SPLIT=3 (3xTF32) GEMM, cp.async double-buffered raw staging,
//    hi/lo split on consume, 256 threads (8 warps 2x4), 2 CTAs/SM.
//    EPI 2: fused q/k projection (blockIdx.y selects B/bias/C), C = acc + bias[col]
//    EPI 3: C = acc (raw scores)
// ---------------------------------------------------------------------------
template <int EPI>
__global__ __launch_bounds__(256, 2)
void gemm_async3_kernel(const float* __restrict__ A, int lda, size_t strideA,
                        const float* __restrict__ B, int ldb, size_t strideB,
                        const float* __restrict__ B2,
                        int K,
                        const float* __restrict__ bias,
                        const float* __restrict__ bias2,
                        float* __restrict__ C, int ldc, size_t strideC,
                        float* __restrict__ C2) {
    extern __shared__ uint32_t sm[];
    const uint32_t smem_base = smem_u32(sm);

    const int bt = blockIdx.z;
    const int m0 = blockIdx.x * 128;
    int n0;
    const float* Bsel;
    const float* biassel;
    float* Csel;
    if (EPI == 2) {
        n0 = 0;
        const bool alt = (blockIdx.y != 0);
        Bsel = alt ? B2 : B;
        biassel = alt ? bias2 : bias;
        Csel = alt ? C2 : C;
    } else {
        n0 = blockIdx.y * 128;
        Bsel = B; biassel = bias; Csel = C;
    }

    const float* Ab = A + (size_t)bt * strideA + (size_t)m0 * lda;
    const float* Bb = Bsel + (size_t)bt * strideB + (size_t)n0 * ldb;

    const int t = threadIdx.x;
    const int wid = t >> 5, lane = t & 31;
    const int warp_m = wid & 1, warp_n = wid >> 1;
    const int l4 = lane >> 2, lm = lane & 3;

    const int prow = t >> 1;
    const int pcol = (t & 1) * 16;
    const float* aRow = Ab + (size_t)prow * lda + pcol;
    const float* bRow = Bb + (size_t)prow * ldb + pcol;
    const uint32_t sA0 = smem_base + (prow * LDS_S + pcol) * 4;
    const uint32_t sB0 = sA0 + TILEW * 4;

    float acc[4][4][4];
    #pragma unroll
    for (int mi = 0; mi < 4; mi++)
        #pragma unroll
        for (int ni = 0; ni < 4; ni++)
            #pragma unroll
            for (int r = 0; r < 4; r++) acc[mi][ni][r] = 0.0f;

    const int NCH = K / 32;

    #pragma unroll
    for (int q = 0; q < 4; q++) {
        CP_ASYNC16(sA0 + q * 16, aRow + q * 4);
        CP_ASYNC16(sB0 + q * 16, bRow + q * 4);
    }
    CP_COMMIT();

    for (int ch = 0; ch < NCH; ch++) {
        const int buf = ch & 1;
        if (ch + 1 < NCH) {
            const int k1 = (ch + 1) * 32;
            const uint32_t dA = sA0 + (buf ^ 1) * (2 * TILEW * 4);
            const uint32_t dB = sB0 + (buf ^ 1) * (2 * TILEW * 4);
            #pragma unroll
            for (int q = 0; q < 4; q++) {
                CP_ASYNC16(dA + q * 16, aRow + k1 + q * 4);
                CP_ASYNC16(dB + q * 16, bRow + k1 + q * 4);
            }
            CP_COMMIT();
            CP_WAIT1();
        } else {
            CP_WAIT0();
        }
        __syncthreads();

        const uint32_t* as = sm + buf * 2 * TILEW;
        const uint32_t* bs = as + TILEW;
        #pragma unroll
        for (int g = 0; g < 4; g++) {
            const int kk = g * 8;
            uint32_t bh[4][2], bl[4][2];
            #pragma unroll
            for (int ni = 0; ni < 4; ni++) {
                const int base = (warp_n * 32 + ni * 8 + l4) * LDS_S + kk + lm;
                const uint32_t r0 = bs[base], r1 = bs[base + 4];
                bh[ni][0] = u2tf(r0);
                bl[ni][0] = f2tf(__uint_as_float(r0) - __uint_as_float(bh[ni][0]));
                bh[ni][1] = u2tf(r1);
                bl[ni][1] = f2tf(__uint_as_float(r1) - __uint_as_float(bh[ni][1]));
            }
            #pragma unroll
            for (int mi = 0; mi < 4; mi++) {
                const int base = (warp_m * 64 + mi * 16 + l4) * LDS_S + kk + lm;
                uint32_t ar[4];
                ar[0] = as[base];
                ar[1] = as[base + 8 * LDS_S];
                ar[2] = as[base + 4];
                ar[3] = as[base + 8 * LDS_S + 4];
                uint32_t ah[4], al[4];
                #pragma unroll
                for (int r = 0; r < 4; r++) {
                    ah[r] = u2tf(ar[r]);
                    al[r] = f2tf(__uint_as_float(ar[r]) - __uint_as_float(ah[r]));
                }
                #pragma unroll
                for (int ni = 0; ni < 4; ni++) {
                    mma_tf32(acc[mi][ni], ah, bl[ni]);
                    mma_tf32(acc[mi][ni], al, bh[ni]);
                    mma_tf32(acc[mi][ni], ah, bh[ni]);
                }
            }
        }
        __syncthreads();
    }

    float* Cb = Csel + (size_t)bt * strideC;
    if (EPI == 2) {
        #pragma unroll
        for (int mi = 0; mi < 4; mi++) {
            const int gr = m0 + warp_m * 64 + mi * 16 + l4;
            #pragma unroll
            for (int ni = 0; ni < 4; ni++) {
                const int gc = n0 + warp_n * 32 + ni * 8 + lm * 2;
                const float b0 = biassel[gc], b1 = biassel[gc + 1];
                float2 o0 = { acc[mi][ni][0] + b0, acc[mi][ni][1] + b1 };
                float2 o1 = { acc[mi][ni][2] + b0, acc[mi][ni][3] + b1 };
                *reinterpret_cast<float2*>(&Cb[(size_t)gr * ldc + gc]) = o0;
                *reinterpret_cast<float2*>(&Cb[(size_t)(gr + 8) * ldc + gc]) = o1;
            }
        }
    } else {
        #pragma unroll
        for (int mi = 0; mi < 4; mi++) {
            const int gr = m0 + warp_m * 64 + mi * 16 + l4;
            #pragma unroll
            for (int ni = 0; ni < 4; ni++) {
                const int gc = n0 + warp_n * 32 + ni * 8 + lm * 2;
                float2 o0 = { acc[mi][ni][0], acc[mi][ni][1] };
                float2 o1 = { acc[mi][ni][2], acc[mi][ni][3] };
                *reinterpret_cast<float2*>(&Cb[(size_t)gr * ldc + gc]) = o0;
                *reinterpret_cast<float2*>(&Cb[(size_t)(gr + 8) * ldc + gc]) = o1;
            }
        }
    }
}

// ---------------------------------------------------------------------------
// Launch
// ---------------------------------------------------------------------------
extern "C" void kernel_launch(void* const* d_in, const int* in_sizes, int n_in,
                              void* d_out, int out_size) {
    const float* img   = (const float*)d_in[0];
    const float* tac   = (const float*)d_in[1];
    const float* Wq    = (const float*)d_in[2];
    const float* bq    = (const float*)d_in[3];
    const float* Wk    = (const float*)d_in[4];
    const float* bk    = (const float*)d_in[5];
    const float* Wv    = (const float*)d_in[6];
    const float* bv    = (const float*)d_in[7];
    const float* gamma = (const float*)d_in[8];
    float* out = (float*)d_out;

    float* gX;  cudaGetSymbolAddress((void**)&gX,  g_X);
    float* gXT; cudaGetSymbolAddress((void**)&gXT, g_XT);
    float* gQT; cudaGetSymbolAddress((void**)&gQT, g_QT);
    float* gKT; cudaGetSymbolAddress((void**)&gKT, g_KT);
    float* gV;  cudaGetSymbolAddress((void**)&gV,  g_V);
    float* gA;  cudaGetSymbolAddress((void**)&gA,  g_ATT);

    cudaFuncSetAttribute(gemm_async_kernel<0>,  cudaFuncAttributeMaxDynamicSharedMemorySize, SMEM_T);
    cudaFuncSetAttribute(gemm_async_kernel<1>,  cudaFuncAttributeMaxDynamicSharedMemorySize, SMEM_T);
    cudaFuncSetAttribute(gemm_async3_kernel<2>, cudaFuncAttributeMaxDynamicSharedMemorySize, SMEM_T);
    cudaFuncSetAttribute(gemm_async3_kernel<3>, cudaFuncAttributeMaxDynamicSharedMemorySize, SMEM_T);

    // 1) fused feature maps
    build_x_kernel <<<dim3((NP + 255) / 256, CF, BT), 256>>>(img, tac);
    build_xt_kernel<<<dim3(CF / 256, NP, BT), 256>>>(img, tac);

    // 2) fused q+k projections (3xTF32, cp.async): QT/KT[n][o] = XT[n][:] @ W^T + b
    gemm_async3_kernel<2><<<dim3(NP / 128, 2, BT), 256, SMEM_T>>>(
        gXT, CF, (size_t)NP * CF,
        Wq, CF, 0, Wk,
        CF, bq, bk,
        gQT, CQ, (size_t)NP * CQ, gKT);

    // 3) v projection (tf32, cp.async, 64x64 warp tile): V[c][n] = Wv @ XT^T + bv
    gemm_async_kernel<0><<<dim3(CF / 128, NP / 128, BT), 128, SMEM_T>>>(
        Wv, CF, 0,
        gXT, CF, (size_t)NP * CF,
        CF, bv, nullptr, nullptr,
        gV, NP, (size_t)CF * NP);

    // 4) attention scores (3xTF32, cp.async): S[n][m] = QT[n][:] @ KT[m][:]^T
    gemm_async3_kernel<3><<<dim3(NP / 128, NP / 128, BT), 256, SMEM_T>>>(
        gQT, CQ, (size_t)NP * CQ,
        gKT, CQ, (size_t)NP * CQ, nullptr,
        CQ, nullptr, nullptr,
        gA, NP, (size_t)NP * NP, nullptr);

    // 5) softmax
    softmax_kernel<<<dim3(NTOK, BT), 256>>>();

    // 6) out = gamma * (V @ P^T) + X (tf32, cp.async, 64x64 warp tile)
    gemm_async_kernel<1><<<dim3(CF / 128, NP / 128, BT), 128, SMEM_T>>>(
        gV, NP, (size_t)CF * NP,
        gA, NP, (size_t)NP * NP,
        NP, nullptr, gamma, gX,
        out, NTOK, (size_t)CF * NTOK);
}

// round 10
// speedup vs baseline: 1.0154x; 1.0154x over previous
#include <cuda_runtime.h>
#include <cstdint>

// ---------------------------------------------------------------------------
// Shapes
// ---------------------------------------------------------------------------
#define BT   12
#define CF   1024
#define CQ   128
#define NTOK 2401
#define NP   2432
#define HF   49

// ---------------------------------------------------------------------------
// Scratch
// ---------------------------------------------------------------------------
__device__ float g_X  [(size_t)BT * CF * NP];   // [bt][c][n]
__device__ float g_XT [(size_t)BT * NP * CF];   // [bt][n][c]
__device__ float g_QT [(size_t)BT * NP * CQ];   // [bt][n][o]
__device__ float g_KT [(size_t)BT * NP * CQ];   // [bt][m][o]
__device__ float g_V  [(size_t)BT * CF * NP];   // [bt][c][n]
__device__ float g_ATT[(size_t)BT * NP * NP];   // [bt][n][m]

__device__ __forceinline__ uint32_t f2tf(float f) {
    uint32_t u; asm("cvt.rna.tf32.f32 %0, %1;" : "=r"(u) : "f"(f)); return u;
}
__device__ __forceinline__ uint32_t u2tf(uint32_t x) {
    uint32_t u; asm("cvt.rna.tf32.f32 %0, %1;" : "=r"(u) : "f"(__uint_as_float(x))); return u;
}
__device__ __forceinline__ uint32_t smem_u32(const void* p) {
    uint32_t a;
    asm("{ .reg .u64 t; cvta.to.shared.u64 t, %1; cvt.u32.u64 %0, t; }" : "=r"(a) : "l"(p));
    return a;
}

__device__ __forceinline__ void mma_tf32(float c[4], const uint32_t a[4], const uint32_t b[2]) {
    asm volatile(
        "mma.sync.aligned.m16n8k8.row.col.f32.tf32.tf32.f32 "
        "{%0,%1,%2,%3}, {%4,%5,%6,%7}, {%8,%9}, {%0,%1,%2,%3};"
        : "+f"(c[0]), "+f"(c[1]), "+f"(c[2]), "+f"(c[3])
        : "r"(a[0]), "r"(a[1]), "r"(a[2]), "r"(a[3]), "r"(b[0]), "r"(b[1]));
}

#define CP_ASYNC16(dst_u32, src_ptr) \
    asm volatile("cp.async.cg.shared.global [%0], [%1], 16;" :: "r"(dst_u32), "l"(src_ptr) : "memory")
#define CP_COMMIT() asm volatile("cp.async.commit_group;" ::: "memory")
#define CP_WAIT0()  asm volatile("cp.async.wait_group 0;" ::: "memory")
#define CP_WAIT1()  asm volatile("cp.async.wait_group 1;" ::: "memory")
#define CP_WAIT2()  asm volatile("cp.async.wait_group 2;" ::: "memory")

// ---------------------------------------------------------------------------
// 1a) X[bt][c][n]  (zero-padded n)
// ---------------------------------------------------------------------------
__global__ void build_x_kernel(const float* __restrict__ img,
                               const float* __restrict__ tac) {
    int n = blockIdx.x * 256 + threadIdx.x;
    int c = blockIdx.y, bt = blockIdx.z;
    if (n >= NP) return;
    float v = 0.0f;
    if (n < NTOK) {
        int i = n / HF, j = n % HF;
        v = (c < 512)
            ? tac[(((size_t)bt * 512 + c) * 7 + (i / 7)) * 7 + (j / 7)]
            : img[(((size_t)bt * 512 + (c - 512)) * 7 + (i % 7)) * 7 + (j % 7)];
    }
    g_X[((size_t)bt * CF + c) * NP + n] = v;
}

// ---------------------------------------------------------------------------
// 1b) XT[bt][n][c]  (zero rows for n >= NTOK)
// ---------------------------------------------------------------------------
__global__ void build_xt_kernel(const float* __restrict__ img,
                                const float* __restrict__ tac) {
    int c = blockIdx.x * 256 + threadIdx.x;
    int n = blockIdx.y, bt = blockIdx.z;
    if (c >= CF) return;
    float v = 0.0f;
    if (n < NTOK) {
        int i = n / HF, j = n % HF;
        v = (c < 512)
            ? tac[(((size_t)bt * 512 + c) * 7 + (i / 7)) * 7 + (j / 7)]
            : img[(((size_t)bt * 512 + (c - 512)) * 7 + (i % 7)) * 7 + (j % 7)];
    }
    g_XT[((size_t)bt * NP + n) * CF + c] = v;
}

// ---------------------------------------------------------------------------
// 2) row softmax (m < 2401), zero padding columns
// ---------------------------------------------------------------------------
__global__ __launch_bounds__(256)
void softmax_kernel() {
    __shared__ float row[NTOK];
    __shared__ float red[256];
    const int n = blockIdx.x, bt = blockIdx.y;
    float* base = g_ATT + ((size_t)bt * NP + n) * NP;
    const int t = threadIdx.x;

    float mx = -1e30f;
    for (int m = t; m < NTOK; m += 256) { float v = base[m]; row[m] = v; mx = fmaxf(mx, v); }
    red[t] = mx; __syncthreads();
    for (int s = 128; s > 0; s >>= 1) { if (t < s) red[t] = fmaxf(red[t], red[t + s]); __syncthreads(); }
    mx = red[0]; __syncthreads();

    float sum = 0.0f;
    for (int m = t; m < NTOK; m += 256) { float e = __expf(row[m] - mx); row[m] = e; sum += e; }
    red[t] = sum; __syncthreads();
    for (int s = 128; s > 0; s >>= 1) { if (t < s) red[t] += red[t + s]; __syncthreads(); }
    float inv = 1.0f / red[0];

    for (int m = t; m < NTOK; m += 256) base[m] = row[m] * inv;
    for (int m = NTOK + t; m < NP; m += 256) base[m] = 0.0f;
}

// ---------------------------------------------------------------------------
// Tiling constants
// ---------------------------------------------------------------------------
#define LDS_S 36
#define TILEW (128 * LDS_S)            // words per 128x32 tile (SPLIT=3 kernel)
#define SMEM_T (4 * TILEW * 4)         // 73728 B (SPLIT=3 double buffer)

// Big-tile SPLIT=1 kernel: 256x128 CTA tile, 3-stage pipeline
#define STAGE_W ((256 + 128) * LDS_S)  // 13824 words per stage (A 256 rows + B 128 rows)
#define BOFF_W  (256 * LDS_S)          // 9216: B region offset within a stage
#define SMEM_BIG (3 * STAGE_W * 4)     // 165888 B

// ---------------------------------------------------------------------------
// 3) SPLIT=1 tf32 GEMM: CTA tile 256x128, 512 threads (16 warps 4Mx4N,
//    warp tile 64x32), 3-stage cp.async pipeline, 1 CTA/SM.
//    C[M,N] = A[M,K] @ B[N,K]^T (both K-major).
//    EPI 0: C = acc + bias[row]
//    EPI 1: C = gamma*acc + X[row][col], col<NTOK
// ---------------------------------------------------------------------------
template <int EPI>
__global__ __launch_bounds__(512, 1)
void gemm_big_kernel(const float* __restrict__ A, int lda, size_t strideA,
                     const float* __restrict__ B, int ldb, size_t strideB,
                     int K,
                     const float* __restrict__ bias,
                     const float* __restrict__ gamma,
                     const float* __restrict__ Xres,
                     float* __restrict__ C, int ldc, size_t strideC) {
    extern __shared__ uint32_t sm[];
    const uint32_t smem_base = smem_u32(sm);

    const int bt = blockIdx.z;
    const int m0 = blockIdx.x * 256;
    const int n0 = blockIdx.y * 128;
    const float* Ab = A + (size_t)bt * strideA + (size_t)m0 * lda;
    const float* Bb = B + (size_t)bt * strideB + (size_t)n0 * ldb;

    const int t = threadIdx.x;
    const int wid = t >> 5, lane = t & 31;
    const int warp_m = wid & 3, warp_n = wid >> 2;   // 4 x 4
    const int l4 = lane >> 2, lm = lane & 3;

    // producer mapping:
    //  threads 0..255  : A row t,        8 x 16B cp.async per stage
    //  threads 256..511: B row (t-256)/2, half (t&1), 4 x 16B per stage
    const bool isA = (t < 256);
    const float* gRow;
    uint32_t sDst;
    if (isA) {
        gRow = Ab + (size_t)t * lda;
        sDst = smem_base + (uint32_t)(t * LDS_S) * 4u;
    } else {
        const int r = (t - 256) >> 1, half = t & 1;
        gRow = Bb + (size_t)r * ldb + half * 16;
        sDst = smem_base + (uint32_t)(BOFF_W + r * LDS_S + half * 16) * 4u;
    }

    float acc[4][4][4];
    #pragma unroll
    for (int mi = 0; mi < 4; mi++)
        #pragma unroll
        for (int ni = 0; ni < 4; ni++)
            #pragma unroll
            for (int r = 0; r < 4; r++) acc[mi][ni][r] = 0.0f;

    const int NCH = K / 32;

    // issue one stage's loads for chunk k-offset koff into stage slot stg
    #define ISSUE_STAGE(stg, koff) do {                                        \
        const uint32_t _d = sDst + (uint32_t)(stg) * (STAGE_W * 4);            \
        if (isA) {                                                             \
            _Pragma("unroll")                                                  \
            for (int q = 0; q < 8; q++)                                        \
                CP_ASYNC16(_d + q * 16, gRow + (koff) + q * 4);                \
        } else {                                                               \
            _Pragma("unroll")                                                  \
            for (int q = 0; q < 4; q++)                                        \
                CP_ASYNC16(_d + q * 16, gRow + (koff) + q * 4);                \
        }                                                                      \
        CP_COMMIT();                                                           \
    } while (0)

    ISSUE_STAGE(0, 0);
    ISSUE_STAGE(1, 32);

    for (int ch = 0; ch < NCH; ch++) {
        const int buf = ch % 3;
        if (ch + 2 < NCH) {
            ISSUE_STAGE((ch + 2) % 3, (ch + 2) * 32);
            CP_WAIT2();
        } else if (ch + 1 < NCH) {
            CP_WAIT1();
        } else {
            CP_WAIT0();
        }
        __syncthreads();

        const uint32_t* as = sm + buf * STAGE_W;
        const uint32_t* bs = as + BOFF_W;
        #pragma unroll
        for (int g = 0; g < 4; g++) {
            const int kk = g * 8;
            uint32_t b[4][2];
            #pragma unroll
            for (int ni = 0; ni < 4; ni++) {
                const int base = (warp_n * 32 + ni * 8 + l4) * LDS_S + kk + lm;
                b[ni][0] = u2tf(bs[base]);
                b[ni][1] = u2tf(bs[base + 4]);
            }
            #pragma unroll
            for (int mi = 0; mi < 4; mi++) {
                const int base = (warp_m * 64 + mi * 16 + l4) * LDS_S + kk + lm;
                uint32_t a[4];
                a[0] = u2tf(as[base]);
                a[1] = u2tf(as[base + 8 * LDS_S]);
                a[2] = u2tf(as[base + 4]);
                a[3] = u2tf(as[base + 8 * LDS_S + 4]);
                #pragma unroll
                for (int ni = 0; ni < 4; ni++) mma_tf32(acc[mi][ni], a, b[ni]);
            }
        }
        __syncthreads();
    }
    #undef ISSUE_STAGE

    float* Cb = C + (size_t)bt * strideC;
    if (EPI == 0) {
        #pragma unroll
        for (int mi = 0; mi < 4; mi++) {
            const int gr = m0 + warp_m * 64 + mi * 16 + l4;
            const float bv0 = bias[gr], bv8 = bias[gr + 8];
            #pragma unroll
            for (int ni = 0; ni < 4; ni++) {
                const int gc = n0 + warp_n * 32 + ni * 8 + lm * 2;
                float2 o0 = { acc[mi][ni][0] + bv0, acc[mi][ni][1] + bv0 };
                float2 o1 = { acc[mi][ni][2] + bv8, acc[mi][ni][3] + bv8 };
                *reinterpret_cast<float2*>(&Cb[(size_t)gr * ldc + gc]) = o0;
                *reinterpret_cast<float2*>(&Cb[(size_t)(gr + 8) * ldc + gc]) = o1;
            }
        }
    } else {
        const float g = __ldg(gamma);
        const float* Xb = Xres + (size_t)bt * CF * NP;
        #pragma unroll
        for (int mi = 0; mi < 4; mi++) {
            const int gr = m0 + warp_m * 64 + mi * 16 + l4;
            #pragma unroll
            for (int ni = 0; ni < 4; ni++) {
                const int gc = n0 + warp_n * 32 + ni * 8 + lm * 2;
                if (gc < NTOK)
                    Cb[(size_t)gr * ldc + gc] = g * acc[mi][ni][0] + Xb[(size_t)gr * NP + gc];
                if (gc + 1 < NTOK)
                    Cb[(size_t)gr * ldc + gc + 1] = g * acc[mi][ni][1] + Xb[(size_t)gr * NP + gc + 1];
                if (gc < NTOK)
                    Cb[(size_t)(gr + 8) * ldc + gc] = g * acc[mi][ni][2] + Xb[(size_t)(gr + 8) * NP + gc];
                if (gc + 1 < NTOK)
                    Cb[(size_t)(gr + 8) * ldc + gc + 1] = g * acc[mi][ni][3] + Xb[(size_t)(gr + 8) * NP + gc + 1];
            }
        }
    }
}

// ---------------------------------------------------------------------------
// 4) SPLIT=3 (3xTF32) GEMM, cp.async double-buffered raw staging,
//    hi/lo split on consume, 256 threads (8 warps 2x4), 2 CTAs/SM. (R8 form)
//    EPI 2: fused q/k projection (blockIdx.y selects B/bias/C), C = acc + bias[col]
//    EPI 3: C = acc (raw scores)
// ---------------------------------------------------------------------------
template <int EPI>
__global__ __launch_bounds__(256, 2)
void gemm_async3_kernel(const float* __restrict__ A, int lda, size_t strideA,
                        const float* __restrict__ B, int ldb, size_t strideB,
                        const float* __restrict__ B2,
                        int K,
                        const float* __restrict__ bias,
                        const float* __restrict__ bias2,
                        float* __restrict__ C, int ldc, size_t strideC,
                        float* __restrict__ C2) {
    extern __shared__ uint32_t sm[];
    const uint32_t smem_base = smem_u32(sm);

    const int bt = blockIdx.z;
    const int m0 = blockIdx.x * 128;
    int n0;
    const float* Bsel;
    const float* biassel;
    float* Csel;
    if (EPI == 2) {
        n0 = 0;
        const bool alt = (blockIdx.y != 0);
        Bsel = alt ? B2 : B;
        biassel = alt ? bias2 : bias;
        Csel = alt ? C2 : C;
    } else {
        n0 = blockIdx.y * 128;
        Bsel = B; biassel = bias; Csel = C;
    }

    const float* Ab = A + (size_t)bt * strideA + (size_t)m0 * lda;
    const float* Bb = Bsel + (size_t)bt * strideB + (size_t)n0 * ldb;

    const int t = threadIdx.x;
    const int wid = t >> 5, lane = t & 31;
    const int warp_m = wid & 1, warp_n = wid >> 1;
    const int l4 = lane >> 2, lm = lane & 3;

    const int prow = t >> 1;
    const int pcol = (t & 1) * 16;
    const float* aRow = Ab + (size_t)prow * lda + pcol;
    const float* bRow = Bb + (size_t)prow * ldb + pcol;
    const uint32_t sA0 = smem_base + (prow * LDS_S + pcol) * 4;
    const uint32_t sB0 = sA0 + TILEW * 4;

    float acc[4][4][4];
    #pragma unroll
    for (int mi = 0; mi < 4; mi++)
        #pragma unroll
        for (int ni = 0; ni < 4; ni++)
            #pragma unroll
            for (int r = 0; r < 4; r++) acc[mi][ni][r] = 0.0f;

    const int NCH = K / 32;

    #pragma unroll
    for (int q = 0; q < 4; q++) {
        CP_ASYNC16(sA0 + q * 16, aRow + q * 4);
        CP_ASYNC16(sB0 + q * 16, bRow + q * 4);
    }
    CP_COMMIT();

    for (int ch = 0; ch < NCH; ch++) {
        const int buf = ch & 1;
        if (ch + 1 < NCH) {
            const int k1 = (ch + 1) * 32;
            const uint32_t dA = sA0 + (buf ^ 1) * (2 * TILEW * 4);
            const uint32_t dB = sB0 + (buf ^ 1) * (2 * TILEW * 4);
            #pragma unroll
            for (int q = 0; q < 4; q++) {
                CP_ASYNC16(dA + q * 16, aRow + k1 + q * 4);
                CP_ASYNC16(dB + q * 16, bRow + k1 + q * 4);
            }
            CP_COMMIT();
            CP_WAIT1();
        } else {
            CP_WAIT0();
        }
        __syncthreads();

        const uint32_t* as = sm + buf * 2 * TILEW;
        const uint32_t* bs = as + TILEW;
        #pragma unroll
        for (int g = 0; g < 4; g++) {
            const int kk = g * 8;
            uint32_t bh[4][2], bl[4][2];
            #pragma unroll
            for (int ni = 0; ni < 4; ni++) {
                const int base = (warp_n * 32 + ni * 8 + l4) * LDS_S + kk + lm;
                const uint32_t r0 = bs[base], r1 = bs[base + 4];
                bh[ni][0] = u2tf(r0);
                bl[ni][0] = f2tf(__uint_as_float(r0) - __uint_as_float(bh[ni][0]));
                bh[ni][1] = u2tf(r1);
                bl[ni][1] = f2tf(__uint_as_float(r1) - __uint_as_float(bh[ni][1]));
            }
            #pragma unroll
            for (int mi = 0; mi < 4; mi++) {
                const int base = (warp_m * 64 + mi * 16 + l4) * LDS_S + kk + lm;
                uint32_t ar[4];
                ar[0] = as[base];
                ar[1] = as[base + 8 * LDS_S];
                ar[2] = as[base + 4];
                ar[3] = as[base + 8 * LDS_S + 4];
                uint32_t ah[4], al[4];
                #pragma unroll
                for (int r = 0; r < 4; r++) {
                    ah[r] = u2tf(ar[r]);
                    al[r] = f2tf(__uint_as_float(ar[r]) - __uint_as_float(ah[r]));
                }
                #pragma unroll
                for (int ni = 0; ni < 4; ni++) {
                    mma_tf32(acc[mi][ni], ah, bl[ni]);
                    mma_tf32(acc[mi][ni], al, bh[ni]);
                    mma_tf32(acc[mi][ni], ah, bh[ni]);
                }
            }
        }
        __syncthreads();
    }

    float* Cb = Csel + (size_t)bt * strideC;
    if (EPI == 2) {
        #pragma unroll
        for (int mi = 0; mi < 4; mi++) {
            const int gr = m0 + warp_m * 64 + mi * 16 + l4;
            #pragma unroll
            for (int ni = 0; ni < 4; ni++) {
                const int gc = n0 + warp_n * 32 + ni * 8 + lm * 2;
                const float b0 = biassel[gc], b1 = biassel[gc + 1];
                float2 o0 = { acc[mi][ni][0] + b0, acc[mi][ni][1] + b1 };
                float2 o1 = { acc[mi][ni][2] + b0, acc[mi][ni][3] + b1 };
                *reinterpret_cast<float2*>(&Cb[(size_t)gr * ldc + gc]) = o0;
                *reinterpret_cast<float2*>(&Cb[(size_t)(gr + 8) * ldc + gc]) = o1;
            }
        }
    } else {
        #pragma unroll
        for (int mi = 0; mi < 4; mi++) {
            const int gr = m0 + warp_m * 64 + mi * 16 + l4;
            #pragma unroll
            for (int ni = 0; ni < 4; ni++) {
                const int gc = n0 + warp_n * 32 + ni * 8 + lm * 2;
                float2 o0 = { acc[mi][ni][0], acc[mi][ni][1] };
                float2 o1 = { acc[mi][ni][2], acc[mi][ni][3] };
                *reinterpret_cast<float2*>(&Cb[(size_t)gr * ldc + gc]) = o0;
                *reinterpret_cast<float2*>(&Cb[(size_t)(gr + 8) * ldc + gc]) = o1;
            }
        }
    }
}

// ---------------------------------------------------------------------------
// Launch
// ---------------------------------------------------------------------------
extern "C" void kernel_launch(void* const* d_in, const int* in_sizes, int n_in,
                              void* d_out, int out_size) {
    const float* img   = (const float*)d_in[0];
    const float* tac   = (const float*)d_in[1];
    const float* Wq    = (const float*)d_in[2];
    const float* bq    = (const float*)d_in[3];
    const float* Wk    = (const float*)d_in[4];
    const float* bk    = (const float*)d_in[5];
    const float* Wv    = (const float*)d_in[6];
    const float* bv    = (const float*)d_in[7];
    const float* gamma = (const float*)d_in[8];
    float* out = (float*)d_out;

    float* gX;  cudaGetSymbolAddress((void**)&gX,  g_X);
    float* gXT; cudaGetSymbolAddress((void**)&gXT, g_XT);
    float* gQT; cudaGetSymbolAddress((void**)&gQT, g_QT);
    float* gKT; cudaGetSymbolAddress((void**)&gKT, g_KT);
    float* gV;  cudaGetSymbolAddress((void**)&gV,  g_V);
    float* gA;  cudaGetSymbolAddress((void**)&gA,  g_ATT);

    cudaFuncSetAttribute(gemm_big_kernel<0>,    cudaFuncAttributeMaxDynamicSharedMemorySize, SMEM_BIG);
    cudaFuncSetAttribute(gemm_big_kernel<1>,    cudaFuncAttributeMaxDynamicSharedMemorySize, SMEM_BIG);
    cudaFuncSetAttribute(gemm_async3_kernel<2>, cudaFuncAttributeMaxDynamicSharedMemorySize, SMEM_T);
    cudaFuncSetAttribute(gemm_async3_kernel<3>, cudaFuncAttributeMaxDynamicSharedMemorySize, SMEM_T);

    // 1) fused feature maps
    build_x_kernel <<<dim3((NP + 255) / 256, CF, BT), 256>>>(img, tac);
    build_xt_kernel<<<dim3(CF / 256, NP, BT), 256>>>(img, tac);

    // 2) fused q+k projections (3xTF32, cp.async): QT/KT[n][o] = XT[n][:] @ W^T + b
    gemm_async3_kernel<2><<<dim3(NP / 128, 2, BT), 256, SMEM_T>>>(
        gXT, CF, (size_t)NP * CF,
        Wq, CF, 0, Wk,
        CF, bq, bk,
        gQT, CQ, (size_t)NP * CQ, gKT);

    // 3) v projection (tf32, 256x128 tile, 3-stage): V[c][n] = Wv @ XT^T + bv
    gemm_big_kernel<0><<<dim3(CF / 256, NP / 128, BT), 512, SMEM_BIG>>>(
        Wv, CF, 0,
        gXT, CF, (size_t)NP * CF,
        CF, bv, nullptr, nullptr,
        gV, NP, (size_t)CF * NP);

    // 4) attention scores (3xTF32, cp.async): S[n][m] = QT[n][:] @ KT[m][:]^T
    gemm_async3_kernel<3><<<dim3(NP / 128, NP / 128, BT), 256, SMEM_T>>>(
        gQT, CQ, (size_t)NP * CQ,
        gKT, CQ, (size_t)NP * CQ, nullptr,
        CQ, nullptr, nullptr,
        gA, NP, (size_t)NP * NP, nullptr);

    // 5) softmax
    softmax_kernel<<<dim3(NTOK, BT), 256>>>();

    // 6) out = gamma * (V @ P^T) + X (tf32, 256x128 tile, 3-stage)
    gemm_big_kernel<1><<<dim3(CF / 256, NP / 128, BT), 512, SMEM_BIG>>>(
        gV, NP, (size_t)CF * NP,
        gA, NP, (size_t)NP * NP,
        NP, nullptr, gamma, gX,
        out, NTOK, (size_t)CF * NTOK);
}